// round 9
// baseline (speedup 1.0000x reference)
#include <cuda_runtime.h>

// QuantumFeatureExtractor — analytic collapse, float2 x 160-thread probe.
//
// out[b,i] = cos(x[b,i] + theta[i]); 320 outputs. Launch-floor bound (~4us).
// R7 lesson: block time tracks the slowest warp's serial dependent path.
// This probe shortens that path (STG waits on 2 MUFU results, not 4) and
// spreads work over 5 full warps. Constraints kept:
//  - __cosf only (fp64 cos = +1us, R1)
//  - theta scalar-loaded (vector load on 80B d_in[1] traps, R4/R5)
//  - one vector element per thread, no folding (R7 regression)

#define BATCH 16
#define N_QUBITS 20
#define TOTAL (BATCH * N_QUBITS)   // 320
#define NTHREADS (TOTAL / 2)       // 160 threads = 5 full warps

__global__ __launch_bounds__(NTHREADS, 1)
void qfe_kernel(const float2* __restrict__ x2,
                const float* __restrict__ theta,
                float2* __restrict__ out2) {
    int t = threadIdx.x;           // 0..159
    float2 v = x2[t];
    // element base = 2t (even); q0 = (2t) % 20 is even in [0,18], so the
    // pair is theta[q0], theta[q0+1] — never wraps past 20.
    int q0 = (t % (N_QUBITS / 2)) * 2;   // (t % 10) * 2
    float2 r;
    r.x = __cosf(v.x + theta[q0 + 0]);
    r.y = __cosf(v.y + theta[q0 + 1]);
    out2[t] = r;
}

extern "C" void kernel_launch(void* const* d_in, const int* in_sizes, int n_in,
                              void* d_out, int out_size) {
    const float2* x2   = (const float2*)d_in[0];  // [16,20] fp32, 320 elems
    const float* theta = (const float*)d_in[1];   // [20] fp32
    float2* out2 = (float2*)d_out;                // [16,20] fp32
    qfe_kernel<<<1, NTHREADS>>>(x2, theta, out2);
}

// round 10
// speedup vs baseline: 1.0408x; 1.0408x over previous
#include <cuda_runtime.h>

// QuantumFeatureExtractor — analytic collapse, 2D-block vectorized fp32 path.
//
// out[b,i] = cos(x[b,i] + theta[i]); 320 outputs. Launch-floor bound (~4us,
// all pipes 0% in ncu across 6 profiled variants). Final micro-trim: block
// (5,16) makes the theta group = threadIdx.x directly, removing the %5
// IMAD-reciprocal sequence from in front of the dependent theta loads.
// Frozen constraints from earlier rounds:
//  - __cosf only (fp64 cos = +1us on FP64 pipe, R1)
//  - theta scalar-loaded (vector load on 80B d_in[1] traps, R4/R5)
//  - one float4 per thread, work spread across warps, no folding (R7)

#define BATCH 16
#define N_QUBITS 20
#define TOTAL (BATCH * N_QUBITS)   // 320
#define NGROUP (N_QUBITS / 4)      // 5 float4 groups per row

__global__ __launch_bounds__(BATCH * NGROUP, 1)
void qfe_kernel(const float4* __restrict__ x4,
                const float* __restrict__ theta,
                float4* __restrict__ out4) {
    int g = threadIdx.x;               // 0..4  : theta group (q0 = 4g)
    int b = threadIdx.y;               // 0..15 : batch row
    int q0 = g * 4;                    // available immediately (SHF)
    // theta loads can issue with zero preceding arithmetic
    float t0 = theta[q0 + 0];
    float t1 = theta[q0 + 1];
    float t2 = theta[q0 + 2];
    float t3 = theta[q0 + 3];
    int idx = b * NGROUP + g;          // one IMAD
    float4 v = x4[idx];
    float4 r;
    r.x = __cosf(v.x + t0);
    r.y = __cosf(v.y + t1);
    r.z = __cosf(v.z + t2);
    r.w = __cosf(v.w + t3);
    out4[idx] = r;
}

extern "C" void kernel_launch(void* const* d_in, const int* in_sizes, int n_in,
                              void* d_out, int out_size) {
    const float4* x4   = (const float4*)d_in[0];  // [16,20] fp32, 320 elems
    const float* theta = (const float*)d_in[1];   // [20] fp32
    float4* out4 = (float4*)d_out;                // [16,20] fp32
    dim3 blk(NGROUP, BATCH);                      // (5,16) = 80 threads
    qfe_kernel<<<1, blk>>>(x4, theta, out4);
}